// round 15
// baseline (speedup 1.0000x reference)
#include <cuda_runtime.h>
#include <cuda_bf16.h>
#include <cstdint>

// ---------------------------------------------------------------------------
// GAT_25383256720122 : 2-layer GAT + pooling + MLP head.
// R14: fuse GEMM0+GEMM1 into one kernel (h never round-trips through global;
//      stage-2 A operand split straight from registers). Stream topology and
//      all other kernels identical to the 504us R12/R13 winner.
// ---------------------------------------------------------------------------

#define N_NODES 100000
#define E_EDGES 1600000
#define E_TOT   (E_EDGES + N_NODES)
#define F_INPUT 256
#define HD      128
#define G_GR    128
#define NCLS    10
#define NB_SCAN ((N_NODES + 1023) / 1024)   // 98

// ------------------------- device scratch ----------------------------------
__device__ float d_h[N_NODES * HD];
__device__ float d_g[N_NODES * HD];
__device__ float d_hsum[N_NODES * HD];
__device__ float d_as[N_NODES * 2];
__device__ float d_ad[N_NODES * 2];
__device__ int   d_esrc[E_TOT];          // CSR payload: src id per slot
__device__ int   d_deg[N_NODES];
__device__ int   d_rowstart[N_NODES + 1];
__device__ int   d_cursor[N_NODES];
__device__ float d_reprs[G_GR * HD];
__device__ int   d_bsum[NB_SCAN];

// ------------------------- streams/events (created pre-main) ----------------
static cudaStream_t g_s1 = nullptr, g_s2 = nullptr;
static cudaEvent_t  g_evA = nullptr, g_evB = nullptr, g_evC = nullptr;
namespace {
struct StreamInit {
    StreamInit() {
        cudaStreamCreateWithFlags(&g_s1, cudaStreamNonBlocking);
        cudaStreamCreateWithFlags(&g_s2, cudaStreamNonBlocking);
        cudaEventCreateWithFlags(&g_evA, cudaEventDisableTiming);
        cudaEventCreateWithFlags(&g_evB, cudaEventDisableTiming);
        cudaEventCreateWithFlags(&g_evC, cudaEventDisableTiming);
    }
};
static StreamInit g_stream_init;
}

// ------------------------- helpers -----------------------------------------
__device__ __forceinline__ uint32_t smem_u32(const void* p) {
    uint32_t a;
    asm("{ .reg .u64 t; cvta.to.shared.u64 t, %1; cvt.u32.u64 %0, t; }"
        : "=r"(a) : "l"(p));
    return a;
}

__device__ __forceinline__ void ldsm_x4(uint32_t addr, uint32_t* r) {
    asm volatile("ldmatrix.sync.aligned.m8n8.x4.shared.b16 {%0,%1,%2,%3}, [%4];"
        : "=r"(r[0]), "=r"(r[1]), "=r"(r[2]), "=r"(r[3]) : "r"(addr));
}

__device__ __forceinline__ void mma_bf16(float* c, const uint32_t* a,
                                         const uint32_t* b) {
    asm volatile(
        "mma.sync.aligned.m16n8k16.row.col.f32.bf16.bf16.f32 "
        "{%0,%1,%2,%3}, {%4,%5,%6,%7}, {%8,%9}, {%0,%1,%2,%3};"
        : "+f"(c[0]), "+f"(c[1]), "+f"(c[2]), "+f"(c[3])
        : "r"(a[0]), "r"(a[1]), "r"(a[2]), "r"(a[3]), "r"(b[0]), "r"(b[1]));
}

// smem layout (bytes), pitch 72 bf16 = 144 B
#define PITCH    72
#define OFF_AHI  0
#define OFF_ALO  18432
#define OFF_BHI  36864
#define OFF_BLO  55296
#define OFF_V0   73728
#define OFF_V1   74240
#define OFF_V2   74752
#define SMEM_DYN 75264

// ------------------------- init: deg=1 (self-loop), reprs=0 ----------------
__global__ void zero_kernel() {
    int i = blockIdx.x * blockDim.x + threadIdx.x;
    if (i < N_NODES) d_deg[i] = 1;
    if (i < G_GR * HD) d_reprs[i] = 0.f;
}

__global__ void hist_kernel(const int* __restrict__ ei) {
    int i = blockIdx.x * blockDim.x + threadIdx.x;
    if (i < E_EDGES) atomicAdd(&d_deg[ei[E_EDGES + i]], 1);
}

// ------------------------- 2-phase scan ------------------------------------
__global__ __launch_bounds__(1024) void scanA_kernel() {
    __shared__ int ws[32];
    int tid = threadIdx.x, lane = tid & 31, wid = tid >> 5;
    int i = blockIdx.x * 1024 + tid;
    int v = (i < N_NODES) ? d_deg[i] : 0;
    #pragma unroll
    for (int o = 16; o > 0; o >>= 1) v += __shfl_down_sync(0xffffffffu, v, o);
    if (lane == 0) ws[wid] = v;
    __syncthreads();
    if (wid == 0) {
        int s = ws[lane];
        #pragma unroll
        for (int o = 16; o > 0; o >>= 1) s += __shfl_down_sync(0xffffffffu, s, o);
        if (lane == 0) d_bsum[blockIdx.x] = s;
    }
}

__global__ __launch_bounds__(1024) void scanC_kernel() {
    __shared__ int ws[32];
    __shared__ int s_off;
    int tid = threadIdx.x, lane = tid & 31, wid = tid >> 5;
    if (tid < 32) {
        int tot = 0;
        for (int j = tid; j < blockIdx.x; j += 32) tot += d_bsum[j];
        #pragma unroll
        for (int o = 16; o > 0; o >>= 1)
            tot += __shfl_down_sync(0xffffffffu, tot, o);
        if (tid == 0) s_off = tot;
    }
    int i = blockIdx.x * 1024 + tid;
    int v = (i < N_NODES) ? d_deg[i] : 0;
    int x = v;
    #pragma unroll
    for (int o = 1; o < 32; o <<= 1) {
        int y = __shfl_up_sync(0xffffffffu, x, o);
        if (lane >= o) x += y;
    }
    if (lane == 31) ws[wid] = x;
    __syncthreads();
    if (wid == 0) {
        int w = ws[lane];
        #pragma unroll
        for (int o = 1; o < 32; o <<= 1) {
            int y = __shfl_up_sync(0xffffffffu, w, o);
            if (lane >= o) w += y;
        }
        ws[lane] = w;
    }
    __syncthreads();
    int incl = x + (wid > 0 ? ws[wid - 1] : 0) + s_off;
    if (i < N_NODES) {
        d_rowstart[i + 1] = incl;
        d_cursor[i]       = incl - v;
    }
    if (i == 0) d_rowstart[0] = 0;
}

__global__ void scatter_kernel(const int* __restrict__ ei) {
    int i = blockIdx.x * blockDim.x + threadIdx.x;
    if (i < E_EDGES) {
        int s = ei[i], d = ei[E_EDGES + i];
        int p = atomicAdd(&d_cursor[d], 1);
        d_esrc[p] = s;
    } else if (i < E_TOT) {
        int n = i - E_EDGES;
        int p = atomicAdd(&d_cursor[n], 1);
        d_esrc[p] = n;
    }
}

// ------------------------- shared GEMM building blocks ----------------------
// B loader: W[k0..k0+63][n] (row-major [K,128]) -> Bs[n][k] hi/lo
#define LOAD_B_CHUNK(Wp, k0)                                                  \
    {                                                                         \
        int n = tid >> 1;                                                     \
        int kh = (tid & 1) * 32;                                              \
        _Pragma("unroll")                                                     \
        for (int kk = 0; kk < 32; kk += 2) {                                  \
            float v0 = (Wp)[(size_t)((k0) + kh + kk) * 128 + n];              \
            float v1 = (Wp)[(size_t)((k0) + kh + kk + 1) * 128 + n];          \
            __nv_bfloat162 h2 = __floats2bfloat162_rn(v0, v1);                \
            __nv_bfloat162 l2 = __floats2bfloat162_rn(                        \
                v0 - __bfloat162float(h2.x), v1 - __bfloat162float(h2.y));    \
            uint32_t off = (uint32_t)(n * (PITCH * 2) + (kh + kk) * 2);       \
            *(uint32_t*)(sm + OFF_BHI + off) = *(uint32_t*)&h2;               \
            *(uint32_t*)(sm + OFF_BLO + off) = *(uint32_t*)&l2;               \
        }                                                                     \
    }

// MMA compute over the staged 64-K chunk, accumulating into accv
#define MMA_CHUNK(accv)                                                       \
    _Pragma("unroll")                                                         \
    for (int ks = 0; ks < 4; ks++) {                                          \
        uint32_t ah[2][4], al[2][4];                                          \
        _Pragma("unroll")                                                     \
        for (int mt = 0; mt < 2; mt++) {                                      \
            uint32_t aoff = (uint32_t)(                                       \
                (mr * 32 + mt * 16 + (lane & 15)) * (PITCH * 2)               \
                + (ks * 16 + (lane >> 4) * 8) * 2);                           \
            ldsm_x4(sb + OFF_AHI + aoff, ah[mt]);                             \
            ldsm_x4(sb + OFF_ALO + aoff, al[mt]);                             \
        }                                                                     \
        _Pragma("unroll")                                                     \
        for (int np = 0; np < 4; np++) {                                      \
            int n_idx = nc * 64 + np * 16 + (lane & 7) + ((lane >> 4) & 1) * 8; \
            int koff = ks * 16 + ((lane >> 3) & 1) * 8;                       \
            uint32_t boff = (uint32_t)(n_idx * (PITCH * 2) + koff * 2);       \
            uint32_t bh[4], bl[4];                                            \
            ldsm_x4(sb + OFF_BHI + boff, bh);                                 \
            ldsm_x4(sb + OFF_BLO + boff, bl);                                 \
            _Pragma("unroll")                                                 \
            for (int mt = 0; mt < 2; mt++) {                                  \
                mma_bf16(accv[mt][np * 2],     ah[mt], bh);                   \
                mma_bf16(accv[mt][np * 2],     ah[mt], bl);                   \
                mma_bf16(accv[mt][np * 2],     al[mt], bh);                   \
                mma_bf16(accv[mt][np * 2 + 1], ah[mt], bh + 2);               \
                mma_bf16(accv[mt][np * 2 + 1], ah[mt], bl + 2);               \
                mma_bf16(accv[mt][np * 2 + 1], al[mt], bh + 2);               \
            }                                                                 \
        }                                                                     \
    }

// ------------------------- fused GEMM0+GEMM1 --------------------------------
// stage1: h = relu(x@pre_w + pre_b)  (K=256), write hsum=h, keep h in regs
// stage2: g = h@w1 (K=128, A from regs), write g + alpha dots as/ad
__global__ __launch_bounds__(256) void fused_gemm01_kernel(
    const float* __restrict__ A,
    const float* __restrict__ W0, const float* __restrict__ bias,
    const float* __restrict__ W1,
    const float* __restrict__ asrc, const float* __restrict__ adst,
    float* __restrict__ hsum, float* __restrict__ g_out,
    float* __restrict__ as_out, float* __restrict__ ad_out, int M)
{
    extern __shared__ char sm[];
    const uint32_t sb = smem_u32(sm);
    float* sv0 = (float*)(sm + OFF_V0);   // bias
    float* sv1 = (float*)(sm + OFF_V1);   // asrc
    float* sv2 = (float*)(sm + OFF_V2);   // adst

    const int tid = threadIdx.x;
    const int w = tid >> 5;
    const int lane = tid & 31;
    const int mr = w >> 1;
    const int nc = w & 1;
    const int row0 = blockIdx.x * 128;
    const int g = lane >> 2, tg = lane & 3;

    if (tid < 128) {
        sv0[tid] = bias[tid];
        sv1[tid] = asrc[tid];
        sv2[tid] = adst[tid];
    }

    float acc[2][8][4];
    #pragma unroll
    for (int mt = 0; mt < 2; mt++)
        #pragma unroll
        for (int nt = 0; nt < 8; nt++)
            #pragma unroll
            for (int q = 0; q < 4; q++) acc[mt][nt][q] = 0.f;

    // ---- stage 1 mainloop: K=256 (4 chunks of 64) ----
    for (int ch = 0; ch < 4; ch++) {
        const int k0 = ch << 6;
        {
            int c4 = (tid & 15) * 4;
            int rb = tid >> 4;
            #pragma unroll
            for (int i = 0; i < 8; i++) {
                int r = rb + i * 16;
                int gr = row0 + r;
                float4 v = make_float4(0.f, 0.f, 0.f, 0.f);
                if (gr < M) v = *(const float4*)(A + (size_t)gr * F_INPUT + k0 + c4);
                __nv_bfloat162 hA = __floats2bfloat162_rn(v.x, v.y);
                __nv_bfloat162 hB = __floats2bfloat162_rn(v.z, v.w);
                __nv_bfloat162 lA = __floats2bfloat162_rn(
                    v.x - __bfloat162float(hA.x), v.y - __bfloat162float(hA.y));
                __nv_bfloat162 lB = __floats2bfloat162_rn(
                    v.z - __bfloat162float(hB.x), v.w - __bfloat162float(hB.y));
                uint32_t off = (uint32_t)(r * (PITCH * 2) + c4 * 2);
                *(uint2*)(sm + OFF_AHI + off) =
                    make_uint2(*(uint32_t*)&hA, *(uint32_t*)&hB);
                *(uint2*)(sm + OFF_ALO + off) =
                    make_uint2(*(uint32_t*)&lA, *(uint32_t*)&lB);
            }
        }
        LOAD_B_CHUNK(W0, k0);
        __syncthreads();
        MMA_CHUNK(acc);
        __syncthreads();
    }

    // ---- h = relu(acc+bias); write hsum; keep in regs ----
    float hreg[2][8][4];
    #pragma unroll
    for (int mt = 0; mt < 2; mt++) {
        int grA = row0 + mr * 32 + mt * 16 + g;
        int grB = grA + 8;
        #pragma unroll
        for (int nt = 0; nt < 8; nt++) {
            int col = nc * 64 + nt * 8 + 2 * tg;
            hreg[mt][nt][0] = fmaxf(acc[mt][nt][0] + sv0[col], 0.f);
            hreg[mt][nt][1] = fmaxf(acc[mt][nt][1] + sv0[col + 1], 0.f);
            hreg[mt][nt][2] = fmaxf(acc[mt][nt][2] + sv0[col], 0.f);
            hreg[mt][nt][3] = fmaxf(acc[mt][nt][3] + sv0[col + 1], 0.f);
            if (grA < M)
                *(float2*)(hsum + (size_t)grA * 128 + col) =
                    make_float2(hreg[mt][nt][0], hreg[mt][nt][1]);
            if (grB < M)
                *(float2*)(hsum + (size_t)grB * 128 + col) =
                    make_float2(hreg[mt][nt][2], hreg[mt][nt][3]);
        }
    }

    // ---- stage 2 mainloop: g = h @ W1, K=128 (2 chunks), A from hreg ----
    #pragma unroll
    for (int mt = 0; mt < 2; mt++)
        #pragma unroll
        for (int nt = 0; nt < 8; nt++)
            #pragma unroll
            for (int q = 0; q < 4; q++) acc[mt][nt][q] = 0.f;

    for (int ch = 0; ch < 2; ch++) {
        // owner warps (nc == ch) write their h fragments into A smem
        if (nc == ch) {
            #pragma unroll
            for (int mt = 0; mt < 2; mt++) {
                int rA = mr * 32 + mt * 16 + g;
                int rB = rA + 8;
                #pragma unroll
                for (int nt = 0; nt < 8; nt++) {
                    int c = nt * 8 + 2 * tg;  // chunk-local col
                    float v0 = hreg[mt][nt][0], v1 = hreg[mt][nt][1];
                    __nv_bfloat162 h2 = __floats2bfloat162_rn(v0, v1);
                    __nv_bfloat162 l2 = __floats2bfloat162_rn(
                        v0 - __bfloat162float(h2.x), v1 - __bfloat162float(h2.y));
                    uint32_t off = (uint32_t)(rA * (PITCH * 2) + c * 2);
                    *(uint32_t*)(sm + OFF_AHI + off) = *(uint32_t*)&h2;
                    *(uint32_t*)(sm + OFF_ALO + off) = *(uint32_t*)&l2;
                    float v2 = hreg[mt][nt][2], v3 = hreg[mt][nt][3];
                    __nv_bfloat162 h2b = __floats2bfloat162_rn(v2, v3);
                    __nv_bfloat162 l2b = __floats2bfloat162_rn(
                        v2 - __bfloat162float(h2b.x), v3 - __bfloat162float(h2b.y));
                    uint32_t offb = (uint32_t)(rB * (PITCH * 2) + c * 2);
                    *(uint32_t*)(sm + OFF_AHI + offb) = *(uint32_t*)&h2b;
                    *(uint32_t*)(sm + OFF_ALO + offb) = *(uint32_t*)&l2b;
                }
            }
        }
        LOAD_B_CHUNK(W1, ch << 6);
        __syncthreads();
        MMA_CHUNK(acc);
        __syncthreads();
    }

    // ---- stage 2 epilogue: write g, fused alpha dots ----
    #pragma unroll
    for (int mt = 0; mt < 2; mt++) {
        int grA = row0 + mr * 32 + mt * 16 + g;
        int grB = grA + 8;
        float psA = 0.f, pdA = 0.f, psB = 0.f, pdB = 0.f;
        #pragma unroll
        for (int nt = 0; nt < 8; nt++) {
            int col = nc * 64 + nt * 8 + 2 * tg;
            float c0 = acc[mt][nt][0], c1 = acc[mt][nt][1];
            float c2 = acc[mt][nt][2], c3 = acc[mt][nt][3];
            float s0 = sv1[col], s1 = sv1[col + 1];
            float t0 = sv2[col], t1 = sv2[col + 1];
            psA += c0 * s0 + c1 * s1;
            pdA += c0 * t0 + c1 * t1;
            psB += c2 * s0 + c3 * s1;
            pdB += c2 * t0 + c3 * t1;
            if (grA < M) *(float2*)(g_out + (size_t)grA * 128 + col) = make_float2(c0, c1);
            if (grB < M) *(float2*)(g_out + (size_t)grB * 128 + col) = make_float2(c2, c3);
        }
        #pragma unroll
        for (int o = 1; o < 4; o <<= 1) {
            psA += __shfl_xor_sync(0xffffffffu, psA, o);
            pdA += __shfl_xor_sync(0xffffffffu, pdA, o);
            psB += __shfl_xor_sync(0xffffffffu, psB, o);
            pdB += __shfl_xor_sync(0xffffffffu, pdB, o);
        }
        if (tg == 0) {
            if (grA < M) {
                as_out[grA * 2 + nc] = psA;
                ad_out[grA * 2 + nc] = pdA;
            }
            if (grB < M) {
                as_out[grB * 2 + nc] = psB;
                ad_out[grB * 2 + nc] = pdB;
            }
        }
    }
}

// ------------------------- mma.sync GEMM (mode1, for GEMM2) -----------------
__global__ __launch_bounds__(256) void mma_gemm_kernel(
    const float* __restrict__ A, int K,
    const float* __restrict__ W,
    const float* __restrict__ vec0, const float* __restrict__ vec1,
    float* __restrict__ C,
    float* __restrict__ as_out, float* __restrict__ ad_out,
    int M)
{
    extern __shared__ char sm[];
    const uint32_t sb = smem_u32(sm);
    float* sv0 = (float*)(sm + OFF_V0);
    float* sv1 = (float*)(sm + OFF_V1);

    const int tid = threadIdx.x;
    const int w = tid >> 5;
    const int lane = tid & 31;
    const int mr = w >> 1;
    const int nc = w & 1;
    const int row0 = blockIdx.x * 128;
    const int g = lane >> 2, tg = lane & 3;

    if (tid < 128) {
        sv0[tid] = vec0[tid];
        sv1[tid] = vec1[tid];
    }

    float acc[2][8][4];
    #pragma unroll
    for (int mt = 0; mt < 2; mt++)
        #pragma unroll
        for (int nt = 0; nt < 8; nt++)
            #pragma unroll
            for (int q = 0; q < 4; q++) acc[mt][nt][q] = 0.f;

    const int nchunk = K >> 6;
    for (int ch = 0; ch < nchunk; ch++) {
        const int k0 = ch << 6;
        {
            int c4 = (tid & 15) * 4;
            int rb = tid >> 4;
            #pragma unroll
            for (int i = 0; i < 8; i++) {
                int r = rb + i * 16;
                int gr = row0 + r;
                float4 v = make_float4(0.f, 0.f, 0.f, 0.f);
                if (gr < M) v = *(const float4*)(A + (size_t)gr * K + k0 + c4);
                __nv_bfloat162 hA = __floats2bfloat162_rn(v.x, v.y);
                __nv_bfloat162 hB = __floats2bfloat162_rn(v.z, v.w);
                __nv_bfloat162 lA = __floats2bfloat162_rn(
                    v.x - __bfloat162float(hA.x), v.y - __bfloat162float(hA.y));
                __nv_bfloat162 lB = __floats2bfloat162_rn(
                    v.z - __bfloat162float(hB.x), v.w - __bfloat162float(hB.y));
                uint32_t off = (uint32_t)(r * (PITCH * 2) + c4 * 2);
                *(uint2*)(sm + OFF_AHI + off) =
                    make_uint2(*(uint32_t*)&hA, *(uint32_t*)&hB);
                *(uint2*)(sm + OFF_ALO + off) =
                    make_uint2(*(uint32_t*)&lA, *(uint32_t*)&lB);
            }
        }
        LOAD_B_CHUNK(W, k0);
        __syncthreads();
        MMA_CHUNK(acc);
        __syncthreads();
    }

    #pragma unroll
    for (int mt = 0; mt < 2; mt++) {
        int grA = row0 + mr * 32 + mt * 16 + g;
        int grB = grA + 8;
        float psA = 0.f, pdA = 0.f, psB = 0.f, pdB = 0.f;
        #pragma unroll
        for (int nt = 0; nt < 8; nt++) {
            int col = nc * 64 + nt * 8 + 2 * tg;
            float c0 = acc[mt][nt][0], c1 = acc[mt][nt][1];
            float c2 = acc[mt][nt][2], c3 = acc[mt][nt][3];
            float s0 = sv0[col], s1 = sv0[col + 1];
            float t0 = sv1[col], t1 = sv1[col + 1];
            psA += c0 * s0 + c1 * s1;
            pdA += c0 * t0 + c1 * t1;
            psB += c2 * s0 + c3 * s1;
            pdB += c2 * t0 + c3 * t1;
            if (grA < M) *(float2*)(C + (size_t)grA * 128 + col) = make_float2(c0, c1);
            if (grB < M) *(float2*)(C + (size_t)grB * 128 + col) = make_float2(c2, c3);
        }
        #pragma unroll
        for (int o = 1; o < 4; o <<= 1) {
            psA += __shfl_xor_sync(0xffffffffu, psA, o);
            pdA += __shfl_xor_sync(0xffffffffu, pdA, o);
            psB += __shfl_xor_sync(0xffffffffu, psB, o);
            pdB += __shfl_xor_sync(0xffffffffu, pdB, o);
        }
        if (tg == 0) {
            if (grA < M) {
                as_out[grA * 2 + nc] = psA;
                ad_out[grA * 2 + nc] = pdA;
            }
            if (grB < M) {
                as_out[grB * 2 + nc] = psB;
                ad_out[grB * 2 + nc] = pdB;
            }
        }
    }
}

// ------------------------- warp-per-node aggregation ------------------------
__global__ __launch_bounds__(128) void agg_kernel(const float* __restrict__ bias) {
    int n = blockIdx.x * 4 + (threadIdx.x >> 5);
    if (n >= N_NODES) return;
    const int lane = threadIdx.x & 31;
    const int start = d_rowstart[n], end = d_rowstart[n + 1];
    const float2 adn = *(const float2*)&d_ad[n * 2];
    const bool head1 = (lane >= 16);

    float4 acc = make_float4(0.f, 0.f, 0.f, 0.f);
    float wsum = 0.f;

    for (int base = start; base < end; base += 32) {
        int cnt = min(32, end - base);
        int s = 0;
        float w0 = 0.f, w1 = 0.f;
        if (lane < cnt) {
            s = d_esrc[base + lane];
            float2 a = *(const float2*)&d_as[s * 2];
            float v0 = a.x + adn.x;
            float v1 = a.y + adn.y;
            v0 = v0 > 0.f ? v0 : 0.2f * v0;
            v1 = v1 > 0.f ? v1 : 0.2f * v1;
            w0 = __expf(v0);
            w1 = __expf(v1);
        }
        #pragma unroll 4
        for (int i = 0; i < cnt; i++) {
            int   si  = __shfl_sync(0xffffffffu, s,  i);
            float w0i = __shfl_sync(0xffffffffu, w0, i);
            float w1i = __shfl_sync(0xffffffffu, w1, i);
            float wi = head1 ? w1i : w0i;
            float4 gv = *(const float4*)&d_g[(size_t)si * HD + lane * 4];
            acc.x += gv.x * wi;
            acc.y += gv.y * wi;
            acc.z += gv.z * wi;
            acc.w += gv.w * wi;
            wsum  += wi;
        }
    }
    float inv = 1.f / wsum;
    float4 bv = *(const float4*)&bias[lane * 4];
    float4 out;
    out.x = fmaxf(acc.x * inv + bv.x, 0.f);
    out.y = fmaxf(acc.y * inv + bv.y, 0.f);
    out.z = fmaxf(acc.z * inv + bv.z, 0.f);
    out.w = fmaxf(acc.w * inv + bv.w, 0.f);
    size_t o = (size_t)n * HD + lane * 4;
    *(float4*)&d_h[o] = out;
    float4 hs = *(const float4*)&d_hsum[o];
    hs.x += out.x; hs.y += out.y; hs.z += out.z; hs.w += out.w;
    *(float4*)&d_hsum[o] = hs;
}

// ------------------------- pooling (sorted batch) ---------------------------
__global__ __launch_bounds__(128) void pool_kernel(const int* __restrict__ batch) {
    const int CH = 256;
    int n0 = blockIdx.x * CH;
    int t = threadIdx.x;
    int nend = min(n0 + CH, N_NODES);
    int cnt = nend - n0;
    __shared__ int s_b[CH];
    for (int i = t; i < cnt; i += 128) s_b[i] = batch[n0 + i];
    __syncthreads();
    float acc = 0.f;
    int cur = s_b[0];
    for (int k = 0; k < cnt; k++) {
        int b = s_b[k];
        if (b != cur) {
            atomicAdd(&d_reprs[cur * HD + t], acc);
            acc = 0.f;
            cur = b;
        }
        acc += d_hsum[(size_t)(n0 + k) * HD + t];
    }
    atomicAdd(&d_reprs[cur * HD + t], acc);
}

// ------------------------- final MLP + log_softmax --------------------------
__global__ __launch_bounds__(128) void final_kernel(
    const float* __restrict__ W1, const float* __restrict__ b1,
    const float* __restrict__ W2, const float* __restrict__ b2,
    float* __restrict__ out)
{
    int g = blockIdx.x;
    int t = threadIdx.x;
    __shared__ float s_r[HD];
    __shared__ float s_z[HD];
    __shared__ float s_o[NCLS];
    s_r[t] = d_reprs[g * HD + t];
    __syncthreads();
    float acc = b1[t];
    #pragma unroll 4
    for (int k = 0; k < HD; k++) acc += s_r[k] * W1[k * HD + t];
    s_z[t] = fmaxf(acc, 0.f);
    __syncthreads();
    if (t < NCLS) {
        float a = b2[t];
        #pragma unroll 4
        for (int k = 0; k < HD; k++) a += s_z[k] * W2[k * NCLS + t];
        s_o[t] = a;
    }
    __syncthreads();
    if (t == 0) {
        float m = -1e30f;
        for (int c = 0; c < NCLS; c++) m = fmaxf(m, s_o[c]);
        float sum = 0.f;
        for (int c = 0; c < NCLS; c++) sum += expf(s_o[c] - m);
        float lse = m + logf(sum);
        for (int c = 0; c < NCLS; c++) out[g * NCLS + c] = s_o[c] - lse;
    }
}

// ------------------------- launch ------------------------------------------
extern "C" void kernel_launch(void* const* d_in, const int* in_sizes, int n_in,
                              void* d_out, int out_size)
{
    const float* x       = (const float*)d_in[0];
    const int*   ei      = (const int*)d_in[1];
    const int*   batch   = (const int*)d_in[2];
    const float* pre_w   = (const float*)d_in[3];
    const float* pre_b   = (const float*)d_in[4];
    const float* w1      = (const float*)d_in[5];
    const float* asrc1   = (const float*)d_in[6];
    const float* adst1   = (const float*)d_in[7];
    const float* b1      = (const float*)d_in[8];
    const float* w2      = (const float*)d_in[9];
    const float* asrc2   = (const float*)d_in[10];
    const float* adst2   = (const float*)d_in[11];
    const float* b2      = (const float*)d_in[12];
    const float* post_w1 = (const float*)d_in[13];
    const float* post_b1 = (const float*)d_in[14];
    const float* post_w2 = (const float*)d_in[15];
    const float* post_b2 = (const float*)d_in[16];
    float* out = (float*)d_out;

    void *p_h_, *p_g_, *p_hsum_, *p_as_, *p_ad_;
    cudaGetSymbolAddress(&p_h_, d_h);
    cudaGetSymbolAddress(&p_g_, d_g);
    cudaGetSymbolAddress(&p_hsum_, d_hsum);
    cudaGetSymbolAddress(&p_as_, d_as);
    cudaGetSymbolAddress(&p_ad_, d_ad);
    float* p_h    = (float*)p_h_;
    float* p_g    = (float*)p_g_;
    float* p_hsum = (float*)p_hsum_;
    float* p_as   = (float*)p_as_;
    float* p_ad   = (float*)p_ad_;

    cudaFuncSetAttribute(fused_gemm01_kernel,
                         cudaFuncAttributeMaxDynamicSharedMemorySize, SMEM_DYN);
    cudaFuncSetAttribute(mma_gemm_kernel,
                         cudaFuncAttributeMaxDynamicSharedMemorySize, SMEM_DYN);

    const int TPB = 256;
    const int eblocks = (E_TOT + TPB - 1) / TPB;
    const int gb = (N_NODES + 127) / 128;

    cudaStream_t s1 = g_s1, s2 = g_s2;

    // fork both worker streams from the capture-origin (legacy) stream
    cudaEventRecord(g_evA, 0);
    cudaStreamWaitEvent(s1, g_evA, 0);
    cudaStreamWaitEvent(s2, g_evA, 0);

    // ---- stream s2: graph build chain ----
    zero_kernel<<<(N_NODES + TPB - 1) / TPB, TPB, 0, s2>>>();
    hist_kernel<<<(E_EDGES + TPB - 1) / TPB, TPB, 0, s2>>>(ei);
    scanA_kernel<<<NB_SCAN, 1024, 0, s2>>>();
    scanC_kernel<<<NB_SCAN, 1024, 0, s2>>>();
    scatter_kernel<<<eblocks, TPB, 0, s2>>>(ei);
    cudaEventRecord(g_evB, s2);

    // ---- stream s1: fused GEMM0+GEMM1 (independent of build) ----
    fused_gemm01_kernel<<<gb, 256, SMEM_DYN, s1>>>(
        x, pre_w, pre_b, w1, asrc1, adst1,
        p_hsum, p_g, p_as, p_ad, N_NODES);

    // join: aggregation needs CSR + g/alpha
    cudaStreamWaitEvent(s1, g_evB, 0);
    agg_kernel<<<(N_NODES + 3) / 4, 128, 0, s1>>>(b1);

    // GAT layer 2
    mma_gemm_kernel<<<gb, 256, SMEM_DYN, s1>>>(p_h, HD, w2, asrc2, adst2,
                                               p_g, p_as, p_ad, N_NODES);
    agg_kernel<<<(N_NODES + 3) / 4, 128, 0, s1>>>(b2);

    // pooling + head
    pool_kernel<<<(N_NODES + 255) / 256, 128, 0, s1>>>(batch);
    final_kernel<<<G_GR, 128, 0, s1>>>(post_w1, post_b1, post_w2, post_b2, out);

    // join back to the capture-origin stream
    cudaEventRecord(g_evC, s1);
    cudaStreamWaitEvent(0, g_evC, 0);
}

// round 16
// speedup vs baseline: 1.0432x; 1.0432x over previous
#include <cuda_runtime.h>
#include <cuda_bf16.h>
#include <cuda_fp16.h>
#include <cstdint>

// ---------------------------------------------------------------------------
// GAT_25383256720122 : 2-layer GAT + pooling + MLP head.
// R15: exact R13 topology/kernels (504us baseline); SINGLE change = g stored
//      fp16 (halves agg gather traffic). Isolates the variable mis-attributed
//      in R9 (which bundled fp16-g with the wsplit regression).
// ---------------------------------------------------------------------------

#define N_NODES 100000
#define E_EDGES 1600000
#define E_TOT   (E_EDGES + N_NODES)
#define F_INPUT 256
#define HD      128
#define G_GR    128
#define NCLS    10
#define NB_SCAN ((N_NODES + 1023) / 1024)   // 98

// ------------------------- device scratch ----------------------------------
__device__ float d_h[N_NODES * HD];
__device__ __half d_gh[N_NODES * HD];    // fp16 g (agg gather payload)
__device__ float d_hsum[N_NODES * HD];
__device__ float d_as[N_NODES * 2];
__device__ float d_ad[N_NODES * 2];
__device__ int   d_esrc[E_TOT];          // CSR payload: src id per slot
__device__ int   d_deg[N_NODES];
__device__ int   d_rowstart[N_NODES + 1];
__device__ int   d_cursor[N_NODES];
__device__ float d_reprs[G_GR * HD];
__device__ int   d_bsum[NB_SCAN];

// ------------------------- streams/events (created pre-main) ----------------
static cudaStream_t g_s1 = nullptr, g_s2 = nullptr;
static cudaEvent_t  g_evA = nullptr, g_evB = nullptr, g_evC = nullptr;
namespace {
struct StreamInit {
    StreamInit() {
        cudaStreamCreateWithFlags(&g_s1, cudaStreamNonBlocking);
        cudaStreamCreateWithFlags(&g_s2, cudaStreamNonBlocking);
        cudaEventCreateWithFlags(&g_evA, cudaEventDisableTiming);
        cudaEventCreateWithFlags(&g_evB, cudaEventDisableTiming);
        cudaEventCreateWithFlags(&g_evC, cudaEventDisableTiming);
    }
};
static StreamInit g_stream_init;
}

// ------------------------- helpers -----------------------------------------
__device__ __forceinline__ uint32_t smem_u32(const void* p) {
    uint32_t a;
    asm("{ .reg .u64 t; cvta.to.shared.u64 t, %1; cvt.u32.u64 %0, t; }"
        : "=r"(a) : "l"(p));
    return a;
}

__device__ __forceinline__ void ldsm_x4(uint32_t addr, uint32_t* r) {
    asm volatile("ldmatrix.sync.aligned.m8n8.x4.shared.b16 {%0,%1,%2,%3}, [%4];"
        : "=r"(r[0]), "=r"(r[1]), "=r"(r[2]), "=r"(r[3]) : "r"(addr));
}

__device__ __forceinline__ void mma_bf16(float* c, const uint32_t* a,
                                         const uint32_t* b) {
    asm volatile(
        "mma.sync.aligned.m16n8k16.row.col.f32.bf16.bf16.f32 "
        "{%0,%1,%2,%3}, {%4,%5,%6,%7}, {%8,%9}, {%0,%1,%2,%3};"
        : "+f"(c[0]), "+f"(c[1]), "+f"(c[2]), "+f"(c[3])
        : "r"(a[0]), "r"(a[1]), "r"(a[2]), "r"(a[3]), "r"(b[0]), "r"(b[1]));
}

// smem layout (bytes), pitch 72 bf16 = 144 B
#define PITCH    72
#define OFF_AHI  0
#define OFF_ALO  18432
#define OFF_BHI  36864
#define OFF_BLO  55296
#define OFF_V0   73728
#define OFF_V1   74240
#define SMEM_DYN 74752

// ------------------------- init: deg=1 (self-loop), reprs=0 ----------------
__global__ void zero_kernel() {
    int i = blockIdx.x * blockDim.x + threadIdx.x;
    if (i < N_NODES) d_deg[i] = 1;
    if (i < G_GR * HD) d_reprs[i] = 0.f;
}

__global__ void hist_kernel(const int* __restrict__ ei) {
    int i = blockIdx.x * blockDim.x + threadIdx.x;
    if (i < E_EDGES) atomicAdd(&d_deg[ei[E_EDGES + i]], 1);
}

// ------------------------- 2-phase scan ------------------------------------
__global__ __launch_bounds__(1024) void scanA_kernel() {
    __shared__ int ws[32];
    int tid = threadIdx.x, lane = tid & 31, wid = tid >> 5;
    int i = blockIdx.x * 1024 + tid;
    int v = (i < N_NODES) ? d_deg[i] : 0;
    #pragma unroll
    for (int o = 16; o > 0; o >>= 1) v += __shfl_down_sync(0xffffffffu, v, o);
    if (lane == 0) ws[wid] = v;
    __syncthreads();
    if (wid == 0) {
        int s = ws[lane];
        #pragma unroll
        for (int o = 16; o > 0; o >>= 1) s += __shfl_down_sync(0xffffffffu, s, o);
        if (lane == 0) d_bsum[blockIdx.x] = s;
    }
}

__global__ __launch_bounds__(1024) void scanC_kernel() {
    __shared__ int ws[32];
    __shared__ int s_off;
    int tid = threadIdx.x, lane = tid & 31, wid = tid >> 5;
    if (tid < 32) {
        int tot = 0;
        for (int j = tid; j < blockIdx.x; j += 32) tot += d_bsum[j];
        #pragma unroll
        for (int o = 16; o > 0; o >>= 1)
            tot += __shfl_down_sync(0xffffffffu, tot, o);
        if (tid == 0) s_off = tot;
    }
    int i = blockIdx.x * 1024 + tid;
    int v = (i < N_NODES) ? d_deg[i] : 0;
    int x = v;
    #pragma unroll
    for (int o = 1; o < 32; o <<= 1) {
        int y = __shfl_up_sync(0xffffffffu, x, o);
        if (lane >= o) x += y;
    }
    if (lane == 31) ws[wid] = x;
    __syncthreads();
    if (wid == 0) {
        int w = ws[lane];
        #pragma unroll
        for (int o = 1; o < 32; o <<= 1) {
            int y = __shfl_up_sync(0xffffffffu, w, o);
            if (lane >= o) w += y;
        }
        ws[lane] = w;
    }
    __syncthreads();
    int incl = x + (wid > 0 ? ws[wid - 1] : 0) + s_off;
    if (i < N_NODES) {
        d_rowstart[i + 1] = incl;
        d_cursor[i]       = incl - v;
    }
    if (i == 0) d_rowstart[0] = 0;
}

__global__ void scatter_kernel(const int* __restrict__ ei) {
    int i = blockIdx.x * blockDim.x + threadIdx.x;
    if (i < E_EDGES) {
        int s = ei[i], d = ei[E_EDGES + i];
        int p = atomicAdd(&d_cursor[d], 1);
        d_esrc[p] = s;
    } else if (i < E_TOT) {
        int n = i - E_EDGES;
        int p = atomicAdd(&d_cursor[n], 1);
        d_esrc[p] = n;
    }
}

// ------------------------- mma.sync GEMM -----------------------------------
// C[M,128] = A[M,K] @ W[K,128], bf16 hi/lo split (3 mma terms).
// mode 0: C = relu(A@W + vec0) fp32, Caux = C.
// mode 1: Cg = A@W raw (fp16); fused alpha dots: as_out/ad_out [M,2].
__global__ __launch_bounds__(256) void mma_gemm_kernel(
    const float* __restrict__ A, int K,
    const float* __restrict__ W,
    const float* __restrict__ vec0, const float* __restrict__ vec1,
    float* __restrict__ C, float* __restrict__ Caux, __half* __restrict__ Cg,
    float* __restrict__ as_out, float* __restrict__ ad_out,
    int M, int mode)
{
    extern __shared__ char sm[];
    const uint32_t sb = smem_u32(sm);
    float* sv0 = (float*)(sm + OFF_V0);
    float* sv1 = (float*)(sm + OFF_V1);

    const int tid = threadIdx.x;
    const int w = tid >> 5;
    const int lane = tid & 31;
    const int mr = w >> 1;          // 0..3 : warp M-row
    const int nc = w & 1;           // 0..1 : warp N-col (== attention head)
    const int row0 = blockIdx.x * 128;
    const int g = lane >> 2, tg = lane & 3;

    if (tid < 128) {
        sv0[tid] = vec0 ? vec0[tid] : 0.f;
        sv1[tid] = vec1 ? vec1[tid] : 0.f;
    }

    float acc[2][8][4];
    #pragma unroll
    for (int mt = 0; mt < 2; mt++)
        #pragma unroll
        for (int nt = 0; nt < 8; nt++)
            #pragma unroll
            for (int q = 0; q < 4; q++) acc[mt][nt][q] = 0.f;

    const int nchunk = K >> 6;
    for (int ch = 0; ch < nchunk; ch++) {
        const int k0 = ch << 6;
        // ---- load+split A: 128 rows x 64 cols ----
        {
            int c4 = (tid & 15) * 4;
            int rb = tid >> 4;
            #pragma unroll
            for (int i = 0; i < 8; i++) {
                int r = rb + i * 16;
                int gr = row0 + r;
                float4 v = make_float4(0.f, 0.f, 0.f, 0.f);
                if (gr < M) v = *(const float4*)(A + (size_t)gr * K + k0 + c4);
                __nv_bfloat162 hA = __floats2bfloat162_rn(v.x, v.y);
                __nv_bfloat162 hB = __floats2bfloat162_rn(v.z, v.w);
                __nv_bfloat162 lA = __floats2bfloat162_rn(
                    v.x - __bfloat162float(hA.x), v.y - __bfloat162float(hA.y));
                __nv_bfloat162 lB = __floats2bfloat162_rn(
                    v.z - __bfloat162float(hB.x), v.w - __bfloat162float(hB.y));
                uint32_t off = (uint32_t)(r * (PITCH * 2) + c4 * 2);
                *(uint2*)(sm + OFF_AHI + off) =
                    make_uint2(*(uint32_t*)&hA, *(uint32_t*)&hB);
                *(uint2*)(sm + OFF_ALO + off) =
                    make_uint2(*(uint32_t*)&lA, *(uint32_t*)&lB);
            }
        }
        // ---- load+split B: W[k0..k0+63][n] -> Bs[n][k] ----
        {
            int n = tid >> 1;
            int kh = (tid & 1) * 32;
            #pragma unroll
            for (int kk = 0; kk < 32; kk += 2) {
                float v0 = W[(size_t)(k0 + kh + kk) * 128 + n];
                float v1 = W[(size_t)(k0 + kh + kk + 1) * 128 + n];
                __nv_bfloat162 h2 = __floats2bfloat162_rn(v0, v1);
                __nv_bfloat162 l2 = __floats2bfloat162_rn(
                    v0 - __bfloat162float(h2.x), v1 - __bfloat162float(h2.y));
                uint32_t off = (uint32_t)(n * (PITCH * 2) + (kh + kk) * 2);
                *(uint32_t*)(sm + OFF_BHI + off) = *(uint32_t*)&h2;
                *(uint32_t*)(sm + OFF_BLO + off) = *(uint32_t*)&l2;
            }
        }
        __syncthreads();

        // ---- compute: 4 k-steps of 16 ----
        #pragma unroll
        for (int ks = 0; ks < 4; ks++) {
            uint32_t ah[2][4], al[2][4];
            #pragma unroll
            for (int mt = 0; mt < 2; mt++) {
                uint32_t aoff = (uint32_t)(
                    (mr * 32 + mt * 16 + (lane & 15)) * (PITCH * 2)
                    + (ks * 16 + (lane >> 4) * 8) * 2);
                ldsm_x4(sb + OFF_AHI + aoff, ah[mt]);
                ldsm_x4(sb + OFF_ALO + aoff, al[mt]);
            }
            #pragma unroll
            for (int np = 0; np < 4; np++) {
                int n_idx = nc * 64 + np * 16 + (lane & 7) + ((lane >> 4) & 1) * 8;
                int koff = ks * 16 + ((lane >> 3) & 1) * 8;
                uint32_t boff = (uint32_t)(n_idx * (PITCH * 2) + koff * 2);
                uint32_t bh[4], bl[4];
                ldsm_x4(sb + OFF_BHI + boff, bh);
                ldsm_x4(sb + OFF_BLO + boff, bl);
                #pragma unroll
                for (int mt = 0; mt < 2; mt++) {
                    mma_bf16(acc[mt][np * 2],     ah[mt], bh);
                    mma_bf16(acc[mt][np * 2],     ah[mt], bl);
                    mma_bf16(acc[mt][np * 2],     al[mt], bh);
                    mma_bf16(acc[mt][np * 2 + 1], ah[mt], bh + 2);
                    mma_bf16(acc[mt][np * 2 + 1], ah[mt], bl + 2);
                    mma_bf16(acc[mt][np * 2 + 1], al[mt], bh + 2);
                }
            }
        }
        __syncthreads();
    }

    // ---- epilogue ----
    #pragma unroll
    for (int mt = 0; mt < 2; mt++) {
        int grA = row0 + mr * 32 + mt * 16 + g;
        int grB = grA + 8;
        if (mode == 0) {
            #pragma unroll
            for (int nt = 0; nt < 8; nt++) {
                int col = nc * 64 + nt * 8 + 2 * tg;
                float2 vA = make_float2(
                    fmaxf(acc[mt][nt][0] + sv0[col], 0.f),
                    fmaxf(acc[mt][nt][1] + sv0[col + 1], 0.f));
                float2 vB = make_float2(
                    fmaxf(acc[mt][nt][2] + sv0[col], 0.f),
                    fmaxf(acc[mt][nt][3] + sv0[col + 1], 0.f));
                if (grA < M) {
                    *(float2*)(C + (size_t)grA * 128 + col) = vA;
                    *(float2*)(Caux + (size_t)grA * 128 + col) = vA;
                }
                if (grB < M) {
                    *(float2*)(C + (size_t)grB * 128 + col) = vB;
                    *(float2*)(Caux + (size_t)grB * 128 + col) = vB;
                }
            }
        } else {
            float psA = 0.f, pdA = 0.f, psB = 0.f, pdB = 0.f;
            #pragma unroll
            for (int nt = 0; nt < 8; nt++) {
                int col = nc * 64 + nt * 8 + 2 * tg;
                float c0 = acc[mt][nt][0], c1 = acc[mt][nt][1];
                float c2 = acc[mt][nt][2], c3 = acc[mt][nt][3];
                float s0 = sv0[col], s1 = sv0[col + 1];
                float t0 = sv1[col], t1 = sv1[col + 1];
                psA += c0 * s0 + c1 * s1;
                pdA += c0 * t0 + c1 * t1;
                psB += c2 * s0 + c3 * s1;
                pdB += c2 * t0 + c3 * t1;
                if (grA < M)
                    *(__half2*)(Cg + (size_t)grA * 128 + col) = __floats2half2_rn(c0, c1);
                if (grB < M)
                    *(__half2*)(Cg + (size_t)grB * 128 + col) = __floats2half2_rn(c2, c3);
            }
            #pragma unroll
            for (int o = 1; o < 4; o <<= 1) {
                psA += __shfl_xor_sync(0xffffffffu, psA, o);
                pdA += __shfl_xor_sync(0xffffffffu, pdA, o);
                psB += __shfl_xor_sync(0xffffffffu, psB, o);
                pdB += __shfl_xor_sync(0xffffffffu, pdB, o);
            }
            if (tg == 0) {
                if (grA < M) {
                    as_out[grA * 2 + nc] = psA;
                    ad_out[grA * 2 + nc] = pdA;
                }
                if (grB < M) {
                    as_out[grB * 2 + nc] = psB;
                    ad_out[grB * 2 + nc] = pdB;
                }
            }
        }
    }
}

// ------------------------- warp-per-node aggregation ------------------------
// Warp owns node n; lane owns cols 4*lane..4*lane+3 (head = lane>>4).
// g gathered in fp16 (half traffic); accumulation fp32.
__global__ __launch_bounds__(128) void agg_kernel(const float* __restrict__ bias) {
    int n = blockIdx.x * 4 + (threadIdx.x >> 5);
    if (n >= N_NODES) return;
    const int lane = threadIdx.x & 31;
    const int start = d_rowstart[n], end = d_rowstart[n + 1];
    const float2 adn = *(const float2*)&d_ad[n * 2];
    const bool head1 = (lane >= 16);

    float4 acc = make_float4(0.f, 0.f, 0.f, 0.f);
    float wsum = 0.f;

    for (int base = start; base < end; base += 32) {
        int cnt = min(32, end - base);
        int s = 0;
        float w0 = 0.f, w1 = 0.f;
        if (lane < cnt) {
            s = d_esrc[base + lane];
            float2 a = *(const float2*)&d_as[s * 2];
            float v0 = a.x + adn.x;
            float v1 = a.y + adn.y;
            v0 = v0 > 0.f ? v0 : 0.2f * v0;
            v1 = v1 > 0.f ? v1 : 0.2f * v1;
            w0 = __expf(v0);
            w1 = __expf(v1);
        }
        #pragma unroll 4
        for (int i = 0; i < cnt; i++) {
            int   si  = __shfl_sync(0xffffffffu, s,  i);
            float w0i = __shfl_sync(0xffffffffu, w0, i);
            float w1i = __shfl_sync(0xffffffffu, w1, i);
            float wi = head1 ? w1i : w0i;
            uint2 gv = *(const uint2*)&d_gh[(size_t)si * HD + lane * 4];
            float2 f01 = __half22float2(*(__half2*)&gv.x);
            float2 f23 = __half22float2(*(__half2*)&gv.y);
            acc.x += f01.x * wi;
            acc.y += f01.y * wi;
            acc.z += f23.x * wi;
            acc.w += f23.y * wi;
            wsum  += wi;
        }
    }
    float inv = 1.f / wsum;
    float4 bv = *(const float4*)&bias[lane * 4];
    float4 out;
    out.x = fmaxf(acc.x * inv + bv.x, 0.f);
    out.y = fmaxf(acc.y * inv + bv.y, 0.f);
    out.z = fmaxf(acc.z * inv + bv.z, 0.f);
    out.w = fmaxf(acc.w * inv + bv.w, 0.f);
    size_t o = (size_t)n * HD + lane * 4;
    *(float4*)&d_h[o] = out;
    float4 hs = *(const float4*)&d_hsum[o];
    hs.x += out.x; hs.y += out.y; hs.z += out.z; hs.w += out.w;
    *(float4*)&d_hsum[o] = hs;
}

// ------------------------- pooling (sorted batch) ---------------------------
__global__ __launch_bounds__(128) void pool_kernel(const int* __restrict__ batch) {
    const int CH = 256;
    int n0 = blockIdx.x * CH;
    int t = threadIdx.x;
    int nend = min(n0 + CH, N_NODES);
    int cnt = nend - n0;
    __shared__ int s_b[CH];
    for (int i = t; i < cnt; i += 128) s_b[i] = batch[n0 + i];
    __syncthreads();
    float acc = 0.f;
    int cur = s_b[0];
    for (int k = 0; k < cnt; k++) {
        int b = s_b[k];
        if (b != cur) {
            atomicAdd(&d_reprs[cur * HD + t], acc);
            acc = 0.f;
            cur = b;
        }
        acc += d_hsum[(size_t)(n0 + k) * HD + t];
    }
    atomicAdd(&d_reprs[cur * HD + t], acc);
}

// ------------------------- final MLP + log_softmax --------------------------
__global__ __launch_bounds__(128) void final_kernel(
    const float* __restrict__ W1, const float* __restrict__ b1,
    const float* __restrict__ W2, const float* __restrict__ b2,
    float* __restrict__ out)
{
    int g = blockIdx.x;
    int t = threadIdx.x;
    __shared__ float s_r[HD];
    __shared__ float s_z[HD];
    __shared__ float s_o[NCLS];
    s_r[t] = d_reprs[g * HD + t];
    __syncthreads();
    float acc = b1[t];
    #pragma unroll 4
    for (int k = 0; k < HD; k++) acc += s_r[k] * W1[k * HD + t];
    s_z[t] = fmaxf(acc, 0.f);
    __syncthreads();
    if (t < NCLS) {
        float a = b2[t];
        #pragma unroll 4
        for (int k = 0; k < HD; k++) a += s_z[k] * W2[k * NCLS + t];
        s_o[t] = a;
    }
    __syncthreads();
    if (t == 0) {
        float m = -1e30f;
        for (int c = 0; c < NCLS; c++) m = fmaxf(m, s_o[c]);
        float sum = 0.f;
        for (int c = 0; c < NCLS; c++) sum += expf(s_o[c] - m);
        float lse = m + logf(sum);
        for (int c = 0; c < NCLS; c++) out[g * NCLS + c] = s_o[c] - lse;
    }
}

// ------------------------- launch ------------------------------------------
extern "C" void kernel_launch(void* const* d_in, const int* in_sizes, int n_in,
                              void* d_out, int out_size)
{
    const float* x       = (const float*)d_in[0];
    const int*   ei      = (const int*)d_in[1];
    const int*   batch   = (const int*)d_in[2];
    const float* pre_w   = (const float*)d_in[3];
    const float* pre_b   = (const float*)d_in[4];
    const float* w1      = (const float*)d_in[5];
    const float* asrc1   = (const float*)d_in[6];
    const float* adst1   = (const float*)d_in[7];
    const float* b1      = (const float*)d_in[8];
    const float* w2      = (const float*)d_in[9];
    const float* asrc2   = (const float*)d_in[10];
    const float* adst2   = (const float*)d_in[11];
    const float* b2      = (const float*)d_in[12];
    const float* post_w1 = (const float*)d_in[13];
    const float* post_b1 = (const float*)d_in[14];
    const float* post_w2 = (const float*)d_in[15];
    const float* post_b2 = (const float*)d_in[16];
    float* out = (float*)d_out;

    void *p_h_, *p_gh_, *p_hsum_, *p_as_, *p_ad_;
    cudaGetSymbolAddress(&p_h_, d_h);
    cudaGetSymbolAddress(&p_gh_, d_gh);
    cudaGetSymbolAddress(&p_hsum_, d_hsum);
    cudaGetSymbolAddress(&p_as_, d_as);
    cudaGetSymbolAddress(&p_ad_, d_ad);
    float*  p_h    = (float*)p_h_;
    __half* p_gh   = (__half*)p_gh_;
    float*  p_hsum = (float*)p_hsum_;
    float*  p_as   = (float*)p_as_;
    float*  p_ad   = (float*)p_ad_;

    cudaFuncSetAttribute(mma_gemm_kernel,
                         cudaFuncAttributeMaxDynamicSharedMemorySize, SMEM_DYN);

    const int TPB = 256;
    const int eblocks = (E_TOT + TPB - 1) / TPB;
    const int gb = (N_NODES + 127) / 128;

    cudaStream_t s1 = g_s1, s2 = g_s2;

    // fork both worker streams from the capture-origin (legacy) stream
    cudaEventRecord(g_evA, 0);
    cudaStreamWaitEvent(s1, g_evA, 0);
    cudaStreamWaitEvent(s2, g_evA, 0);

    // ---- stream s2: graph build chain ----
    zero_kernel<<<(N_NODES + TPB - 1) / TPB, TPB, 0, s2>>>();
    hist_kernel<<<(E_EDGES + TPB - 1) / TPB, TPB, 0, s2>>>(ei);
    scanA_kernel<<<NB_SCAN, 1024, 0, s2>>>();
    scanC_kernel<<<NB_SCAN, 1024, 0, s2>>>();
    scatter_kernel<<<eblocks, TPB, 0, s2>>>(ei);
    cudaEventRecord(g_evB, s2);

    // ---- stream s1: GEMM chain (independent of build) ----
    mma_gemm_kernel<<<gb, 256, SMEM_DYN, s1>>>(x, F_INPUT, pre_w, pre_b, nullptr,
                                               p_h, p_hsum, nullptr, nullptr, nullptr,
                                               N_NODES, 0);
    mma_gemm_kernel<<<gb, 256, SMEM_DYN, s1>>>(p_h, HD, w1, asrc1, adst1,
                                               nullptr, nullptr, p_gh, p_as, p_ad,
                                               N_NODES, 1);

    // join: aggregation needs CSR + GEMM1 results
    cudaStreamWaitEvent(s1, g_evB, 0);
    agg_kernel<<<(N_NODES + 3) / 4, 128, 0, s1>>>(b1);

    // GAT layer 2
    mma_gemm_kernel<<<gb, 256, SMEM_DYN, s1>>>(p_h, HD, w2, asrc2, adst2,
                                               nullptr, nullptr, p_gh, p_as, p_ad,
                                               N_NODES, 1);
    agg_kernel<<<(N_NODES + 3) / 4, 128, 0, s1>>>(b2);

    // pooling + head
    pool_kernel<<<(N_NODES + 255) / 256, 128, 0, s1>>>(batch);
    final_kernel<<<G_GR, 128, 0, s1>>>(post_w1, post_b1, post_w2, post_b2, out);

    // join back to the capture-origin stream
    cudaEventRecord(g_evC, s1);
    cudaStreamWaitEvent(0, g_evC, 0);
}

// round 17
// speedup vs baseline: 1.0945x; 1.0492x over previous
#include <cuda_runtime.h>
#include <cuda_bf16.h>
#include <cstdint>

// ---------------------------------------------------------------------------
// GAT_25383256720122 : 2-layer GAT + pooling + MLP head.
// R16: R13 proven baseline (504us) + dead-store elimination: layer-2 agg
//      skips the d_h write (never read downstream; pool uses d_hsum).
// ---------------------------------------------------------------------------

#define N_NODES 100000
#define E_EDGES 1600000
#define E_TOT   (E_EDGES + N_NODES)
#define F_INPUT 256
#define HD      128
#define G_GR    128
#define NCLS    10
#define NB_SCAN ((N_NODES + 1023) / 1024)   // 98

// ------------------------- device scratch ----------------------------------
__device__ float d_h[N_NODES * HD];
__device__ float d_g[N_NODES * HD];
__device__ float d_hsum[N_NODES * HD];
__device__ float d_as[N_NODES * 2];
__device__ float d_ad[N_NODES * 2];
__device__ int   d_esrc[E_TOT];          // CSR payload: src id per slot
__device__ int   d_deg[N_NODES];
__device__ int   d_rowstart[N_NODES + 1];
__device__ int   d_cursor[N_NODES];
__device__ float d_reprs[G_GR * HD];
__device__ int   d_bsum[NB_SCAN];

// ------------------------- streams/events (created pre-main) ----------------
static cudaStream_t g_s1 = nullptr, g_s2 = nullptr;
static cudaEvent_t  g_evA = nullptr, g_evB = nullptr, g_evC = nullptr;
namespace {
struct StreamInit {
    StreamInit() {
        cudaStreamCreateWithFlags(&g_s1, cudaStreamNonBlocking);
        cudaStreamCreateWithFlags(&g_s2, cudaStreamNonBlocking);
        cudaEventCreateWithFlags(&g_evA, cudaEventDisableTiming);
        cudaEventCreateWithFlags(&g_evB, cudaEventDisableTiming);
        cudaEventCreateWithFlags(&g_evC, cudaEventDisableTiming);
    }
};
static StreamInit g_stream_init;
}

// ------------------------- helpers -----------------------------------------
__device__ __forceinline__ uint32_t smem_u32(const void* p) {
    uint32_t a;
    asm("{ .reg .u64 t; cvta.to.shared.u64 t, %1; cvt.u32.u64 %0, t; }"
        : "=r"(a) : "l"(p));
    return a;
}

__device__ __forceinline__ void ldsm_x4(uint32_t addr, uint32_t* r) {
    asm volatile("ldmatrix.sync.aligned.m8n8.x4.shared.b16 {%0,%1,%2,%3}, [%4];"
        : "=r"(r[0]), "=r"(r[1]), "=r"(r[2]), "=r"(r[3]) : "r"(addr));
}

__device__ __forceinline__ void mma_bf16(float* c, const uint32_t* a,
                                         const uint32_t* b) {
    asm volatile(
        "mma.sync.aligned.m16n8k16.row.col.f32.bf16.bf16.f32 "
        "{%0,%1,%2,%3}, {%4,%5,%6,%7}, {%8,%9}, {%0,%1,%2,%3};"
        : "+f"(c[0]), "+f"(c[1]), "+f"(c[2]), "+f"(c[3])
        : "r"(a[0]), "r"(a[1]), "r"(a[2]), "r"(a[3]), "r"(b[0]), "r"(b[1]));
}

// smem layout (bytes), pitch 72 bf16 = 144 B
#define PITCH    72
#define OFF_AHI  0
#define OFF_ALO  18432
#define OFF_BHI  36864
#define OFF_BLO  55296
#define OFF_V0   73728
#define OFF_V1   74240
#define SMEM_DYN 74752

// ------------------------- init: deg=1 (self-loop), reprs=0 ----------------
__global__ void zero_kernel() {
    int i = blockIdx.x * blockDim.x + threadIdx.x;
    if (i < N_NODES) d_deg[i] = 1;
    if (i < G_GR * HD) d_reprs[i] = 0.f;
}

__global__ void hist_kernel(const int* __restrict__ ei) {
    int i = blockIdx.x * blockDim.x + threadIdx.x;
    if (i < E_EDGES) atomicAdd(&d_deg[ei[E_EDGES + i]], 1);
}

// ------------------------- 2-phase scan ------------------------------------
__global__ __launch_bounds__(1024) void scanA_kernel() {
    __shared__ int ws[32];
    int tid = threadIdx.x, lane = tid & 31, wid = tid >> 5;
    int i = blockIdx.x * 1024 + tid;
    int v = (i < N_NODES) ? d_deg[i] : 0;
    #pragma unroll
    for (int o = 16; o > 0; o >>= 1) v += __shfl_down_sync(0xffffffffu, v, o);
    if (lane == 0) ws[wid] = v;
    __syncthreads();
    if (wid == 0) {
        int s = ws[lane];
        #pragma unroll
        for (int o = 16; o > 0; o >>= 1) s += __shfl_down_sync(0xffffffffu, s, o);
        if (lane == 0) d_bsum[blockIdx.x] = s;
    }
}

__global__ __launch_bounds__(1024) void scanC_kernel() {
    __shared__ int ws[32];
    __shared__ int s_off;
    int tid = threadIdx.x, lane = tid & 31, wid = tid >> 5;
    if (tid < 32) {
        int tot = 0;
        for (int j = tid; j < blockIdx.x; j += 32) tot += d_bsum[j];
        #pragma unroll
        for (int o = 16; o > 0; o >>= 1)
            tot += __shfl_down_sync(0xffffffffu, tot, o);
        if (tid == 0) s_off = tot;
    }
    int i = blockIdx.x * 1024 + tid;
    int v = (i < N_NODES) ? d_deg[i] : 0;
    int x = v;
    #pragma unroll
    for (int o = 1; o < 32; o <<= 1) {
        int y = __shfl_up_sync(0xffffffffu, x, o);
        if (lane >= o) x += y;
    }
    if (lane == 31) ws[wid] = x;
    __syncthreads();
    if (wid == 0) {
        int w = ws[lane];
        #pragma unroll
        for (int o = 1; o < 32; o <<= 1) {
            int y = __shfl_up_sync(0xffffffffu, w, o);
            if (lane >= o) w += y;
        }
        ws[lane] = w;
    }
    __syncthreads();
    int incl = x + (wid > 0 ? ws[wid - 1] : 0) + s_off;
    if (i < N_NODES) {
        d_rowstart[i + 1] = incl;
        d_cursor[i]       = incl - v;
    }
    if (i == 0) d_rowstart[0] = 0;
}

__global__ void scatter_kernel(const int* __restrict__ ei) {
    int i = blockIdx.x * blockDim.x + threadIdx.x;
    if (i < E_EDGES) {
        int s = ei[i], d = ei[E_EDGES + i];
        int p = atomicAdd(&d_cursor[d], 1);
        d_esrc[p] = s;
    } else if (i < E_TOT) {
        int n = i - E_EDGES;
        int p = atomicAdd(&d_cursor[n], 1);
        d_esrc[p] = n;
    }
}

// ------------------------- mma.sync GEMM (R8 exact) -------------------------
// C[M,128] = A[M,K] @ W[K,128], bf16 hi/lo split (3 mma terms).
// mode 0: C = relu(A@W + vec0), Caux = C.
// mode 1: C = A@W raw; fused alpha dots: as_out/ad_out [M,2].
__global__ __launch_bounds__(256) void mma_gemm_kernel(
    const float* __restrict__ A, int K,
    const float* __restrict__ W,
    const float* __restrict__ vec0, const float* __restrict__ vec1,
    float* __restrict__ C, float* __restrict__ Caux,
    float* __restrict__ as_out, float* __restrict__ ad_out,
    int M, int mode)
{
    extern __shared__ char sm[];
    const uint32_t sb = smem_u32(sm);
    float* sv0 = (float*)(sm + OFF_V0);
    float* sv1 = (float*)(sm + OFF_V1);

    const int tid = threadIdx.x;
    const int w = tid >> 5;
    const int lane = tid & 31;
    const int mr = w >> 1;          // 0..3 : warp M-row
    const int nc = w & 1;           // 0..1 : warp N-col (== attention head)
    const int row0 = blockIdx.x * 128;
    const int g = lane >> 2, tg = lane & 3;

    if (tid < 128) {
        sv0[tid] = vec0 ? vec0[tid] : 0.f;
        sv1[tid] = vec1 ? vec1[tid] : 0.f;
    }

    float acc[2][8][4];
    #pragma unroll
    for (int mt = 0; mt < 2; mt++)
        #pragma unroll
        for (int nt = 0; nt < 8; nt++)
            #pragma unroll
            for (int q = 0; q < 4; q++) acc[mt][nt][q] = 0.f;

    const int nchunk = K >> 6;
    for (int ch = 0; ch < nchunk; ch++) {
        const int k0 = ch << 6;
        // ---- load+split A: 128 rows x 64 cols ----
        {
            int c4 = (tid & 15) * 4;
            int rb = tid >> 4;
            #pragma unroll
            for (int i = 0; i < 8; i++) {
                int r = rb + i * 16;
                int gr = row0 + r;
                float4 v = make_float4(0.f, 0.f, 0.f, 0.f);
                if (gr < M) v = *(const float4*)(A + (size_t)gr * K + k0 + c4);
                __nv_bfloat162 hA = __floats2bfloat162_rn(v.x, v.y);
                __nv_bfloat162 hB = __floats2bfloat162_rn(v.z, v.w);
                __nv_bfloat162 lA = __floats2bfloat162_rn(
                    v.x - __bfloat162float(hA.x), v.y - __bfloat162float(hA.y));
                __nv_bfloat162 lB = __floats2bfloat162_rn(
                    v.z - __bfloat162float(hB.x), v.w - __bfloat162float(hB.y));
                uint32_t off = (uint32_t)(r * (PITCH * 2) + c4 * 2);
                *(uint2*)(sm + OFF_AHI + off) =
                    make_uint2(*(uint32_t*)&hA, *(uint32_t*)&hB);
                *(uint2*)(sm + OFF_ALO + off) =
                    make_uint2(*(uint32_t*)&lA, *(uint32_t*)&lB);
            }
        }
        // ---- load+split B: W[k0..k0+63][n] -> Bs[n][k] ----
        {
            int n = tid >> 1;
            int kh = (tid & 1) * 32;
            #pragma unroll
            for (int kk = 0; kk < 32; kk += 2) {
                float v0 = W[(size_t)(k0 + kh + kk) * 128 + n];
                float v1 = W[(size_t)(k0 + kh + kk + 1) * 128 + n];
                __nv_bfloat162 h2 = __floats2bfloat162_rn(v0, v1);
                __nv_bfloat162 l2 = __floats2bfloat162_rn(
                    v0 - __bfloat162float(h2.x), v1 - __bfloat162float(h2.y));
                uint32_t off = (uint32_t)(n * (PITCH * 2) + (kh + kk) * 2);
                *(uint32_t*)(sm + OFF_BHI + off) = *(uint32_t*)&h2;
                *(uint32_t*)(sm + OFF_BLO + off) = *(uint32_t*)&l2;
            }
        }
        __syncthreads();

        // ---- compute: 4 k-steps of 16 ----
        #pragma unroll
        for (int ks = 0; ks < 4; ks++) {
            uint32_t ah[2][4], al[2][4];
            #pragma unroll
            for (int mt = 0; mt < 2; mt++) {
                uint32_t aoff = (uint32_t)(
                    (mr * 32 + mt * 16 + (lane & 15)) * (PITCH * 2)
                    + (ks * 16 + (lane >> 4) * 8) * 2);
                ldsm_x4(sb + OFF_AHI + aoff, ah[mt]);
                ldsm_x4(sb + OFF_ALO + aoff, al[mt]);
            }
            #pragma unroll
            for (int np = 0; np < 4; np++) {
                int n_idx = nc * 64 + np * 16 + (lane & 7) + ((lane >> 4) & 1) * 8;
                int koff = ks * 16 + ((lane >> 3) & 1) * 8;
                uint32_t boff = (uint32_t)(n_idx * (PITCH * 2) + koff * 2);
                uint32_t bh[4], bl[4];
                ldsm_x4(sb + OFF_BHI + boff, bh);
                ldsm_x4(sb + OFF_BLO + boff, bl);
                #pragma unroll
                for (int mt = 0; mt < 2; mt++) {
                    mma_bf16(acc[mt][np * 2],     ah[mt], bh);
                    mma_bf16(acc[mt][np * 2],     ah[mt], bl);
                    mma_bf16(acc[mt][np * 2],     al[mt], bh);
                    mma_bf16(acc[mt][np * 2 + 1], ah[mt], bh + 2);
                    mma_bf16(acc[mt][np * 2 + 1], ah[mt], bl + 2);
                    mma_bf16(acc[mt][np * 2 + 1], al[mt], bh + 2);
                }
            }
        }
        __syncthreads();
    }

    // ---- epilogue ----
    #pragma unroll
    for (int mt = 0; mt < 2; mt++) {
        int grA = row0 + mr * 32 + mt * 16 + g;
        int grB = grA + 8;
        if (mode == 0) {
            #pragma unroll
            for (int nt = 0; nt < 8; nt++) {
                int col = nc * 64 + nt * 8 + 2 * tg;
                float2 vA = make_float2(
                    fmaxf(acc[mt][nt][0] + sv0[col], 0.f),
                    fmaxf(acc[mt][nt][1] + sv0[col + 1], 0.f));
                float2 vB = make_float2(
                    fmaxf(acc[mt][nt][2] + sv0[col], 0.f),
                    fmaxf(acc[mt][nt][3] + sv0[col + 1], 0.f));
                if (grA < M) {
                    *(float2*)(C + (size_t)grA * 128 + col) = vA;
                    *(float2*)(Caux + (size_t)grA * 128 + col) = vA;
                }
                if (grB < M) {
                    *(float2*)(C + (size_t)grB * 128 + col) = vB;
                    *(float2*)(Caux + (size_t)grB * 128 + col) = vB;
                }
            }
        } else {
            float psA = 0.f, pdA = 0.f, psB = 0.f, pdB = 0.f;
            #pragma unroll
            for (int nt = 0; nt < 8; nt++) {
                int col = nc * 64 + nt * 8 + 2 * tg;
                float c0 = acc[mt][nt][0], c1 = acc[mt][nt][1];
                float c2 = acc[mt][nt][2], c3 = acc[mt][nt][3];
                float s0 = sv0[col], s1 = sv0[col + 1];
                float t0 = sv1[col], t1 = sv1[col + 1];
                psA += c0 * s0 + c1 * s1;
                pdA += c0 * t0 + c1 * t1;
                psB += c2 * s0 + c3 * s1;
                pdB += c2 * t0 + c3 * t1;
                if (grA < M) *(float2*)(C + (size_t)grA * 128 + col) = make_float2(c0, c1);
                if (grB < M) *(float2*)(C + (size_t)grB * 128 + col) = make_float2(c2, c3);
            }
            #pragma unroll
            for (int o = 1; o < 4; o <<= 1) {
                psA += __shfl_xor_sync(0xffffffffu, psA, o);
                pdA += __shfl_xor_sync(0xffffffffu, pdA, o);
                psB += __shfl_xor_sync(0xffffffffu, psB, o);
                pdB += __shfl_xor_sync(0xffffffffu, pdB, o);
            }
            if (tg == 0) {
                if (grA < M) {
                    as_out[grA * 2 + nc] = psA;
                    ad_out[grA * 2 + nc] = pdA;
                }
                if (grB < M) {
                    as_out[grB * 2 + nc] = psB;
                    ad_out[grB * 2 + nc] = pdB;
                }
            }
        }
    }
}

// ------------------------- warp-per-node aggregation ------------------------
// store_h: layer-1 agg writes d_h (feeds GEMM2); layer-2 agg skips it (dead).
__global__ __launch_bounds__(128) void agg_kernel(const float* __restrict__ bias,
                                                  int store_h) {
    int n = blockIdx.x * 4 + (threadIdx.x >> 5);
    if (n >= N_NODES) return;
    const int lane = threadIdx.x & 31;
    const int start = d_rowstart[n], end = d_rowstart[n + 1];
    const float2 adn = *(const float2*)&d_ad[n * 2];
    const bool head1 = (lane >= 16);

    float4 acc = make_float4(0.f, 0.f, 0.f, 0.f);
    float wsum = 0.f;

    for (int base = start; base < end; base += 32) {
        int cnt = min(32, end - base);
        int s = 0;
        float w0 = 0.f, w1 = 0.f;
        if (lane < cnt) {
            s = d_esrc[base + lane];
            float2 a = *(const float2*)&d_as[s * 2];
            float v0 = a.x + adn.x;
            float v1 = a.y + adn.y;
            v0 = v0 > 0.f ? v0 : 0.2f * v0;
            v1 = v1 > 0.f ? v1 : 0.2f * v1;
            w0 = __expf(v0);
            w1 = __expf(v1);
        }
        #pragma unroll 4
        for (int i = 0; i < cnt; i++) {
            int   si  = __shfl_sync(0xffffffffu, s,  i);
            float w0i = __shfl_sync(0xffffffffu, w0, i);
            float w1i = __shfl_sync(0xffffffffu, w1, i);
            float wi = head1 ? w1i : w0i;
            float4 gv = *(const float4*)&d_g[(size_t)si * HD + lane * 4];
            acc.x += gv.x * wi;
            acc.y += gv.y * wi;
            acc.z += gv.z * wi;
            acc.w += gv.w * wi;
            wsum  += wi;
        }
    }
    float inv = 1.f / wsum;
    float4 bv = *(const float4*)&bias[lane * 4];
    float4 out;
    out.x = fmaxf(acc.x * inv + bv.x, 0.f);
    out.y = fmaxf(acc.y * inv + bv.y, 0.f);
    out.z = fmaxf(acc.z * inv + bv.z, 0.f);
    out.w = fmaxf(acc.w * inv + bv.w, 0.f);
    size_t o = (size_t)n * HD + lane * 4;
    if (store_h) *(float4*)&d_h[o] = out;
    float4 hs = *(const float4*)&d_hsum[o];
    hs.x += out.x; hs.y += out.y; hs.z += out.z; hs.w += out.w;
    *(float4*)&d_hsum[o] = hs;
}

// ------------------------- pooling (sorted batch) ---------------------------
__global__ __launch_bounds__(128) void pool_kernel(const int* __restrict__ batch) {
    const int CH = 256;
    int n0 = blockIdx.x * CH;
    int t = threadIdx.x;
    int nend = min(n0 + CH, N_NODES);
    int cnt = nend - n0;
    __shared__ int s_b[CH];
    for (int i = t; i < cnt; i += 128) s_b[i] = batch[n0 + i];
    __syncthreads();
    float acc = 0.f;
    int cur = s_b[0];
    for (int k = 0; k < cnt; k++) {
        int b = s_b[k];
        if (b != cur) {
            atomicAdd(&d_reprs[cur * HD + t], acc);
            acc = 0.f;
            cur = b;
        }
        acc += d_hsum[(size_t)(n0 + k) * HD + t];
    }
    atomicAdd(&d_reprs[cur * HD + t], acc);
}

// ------------------------- final MLP + log_softmax --------------------------
__global__ __launch_bounds__(128) void final_kernel(
    const float* __restrict__ W1, const float* __restrict__ b1,
    const float* __restrict__ W2, const float* __restrict__ b2,
    float* __restrict__ out)
{
    int g = blockIdx.x;
    int t = threadIdx.x;
    __shared__ float s_r[HD];
    __shared__ float s_z[HD];
    __shared__ float s_o[NCLS];
    s_r[t] = d_reprs[g * HD + t];
    __syncthreads();
    float acc = b1[t];
    #pragma unroll 4
    for (int k = 0; k < HD; k++) acc += s_r[k] * W1[k * HD + t];
    s_z[t] = fmaxf(acc, 0.f);
    __syncthreads();
    if (t < NCLS) {
        float a = b2[t];
        #pragma unroll 4
        for (int k = 0; k < HD; k++) a += s_z[k] * W2[k * NCLS + t];
        s_o[t] = a;
    }
    __syncthreads();
    if (t == 0) {
        float m = -1e30f;
        for (int c = 0; c < NCLS; c++) m = fmaxf(m, s_o[c]);
        float sum = 0.f;
        for (int c = 0; c < NCLS; c++) sum += expf(s_o[c] - m);
        float lse = m + logf(sum);
        for (int c = 0; c < NCLS; c++) out[g * NCLS + c] = s_o[c] - lse;
    }
}

// ------------------------- launch ------------------------------------------
extern "C" void kernel_launch(void* const* d_in, const int* in_sizes, int n_in,
                              void* d_out, int out_size)
{
    const float* x       = (const float*)d_in[0];
    const int*   ei      = (const int*)d_in[1];
    const int*   batch   = (const int*)d_in[2];
    const float* pre_w   = (const float*)d_in[3];
    const float* pre_b   = (const float*)d_in[4];
    const float* w1      = (const float*)d_in[5];
    const float* asrc1   = (const float*)d_in[6];
    const float* adst1   = (const float*)d_in[7];
    const float* b1      = (const float*)d_in[8];
    const float* w2      = (const float*)d_in[9];
    const float* asrc2   = (const float*)d_in[10];
    const float* adst2   = (const float*)d_in[11];
    const float* b2      = (const float*)d_in[12];
    const float* post_w1 = (const float*)d_in[13];
    const float* post_b1 = (const float*)d_in[14];
    const float* post_w2 = (const float*)d_in[15];
    const float* post_b2 = (const float*)d_in[16];
    float* out = (float*)d_out;

    void *p_h_, *p_g_, *p_hsum_, *p_as_, *p_ad_;
    cudaGetSymbolAddress(&p_h_, d_h);
    cudaGetSymbolAddress(&p_g_, d_g);
    cudaGetSymbolAddress(&p_hsum_, d_hsum);
    cudaGetSymbolAddress(&p_as_, d_as);
    cudaGetSymbolAddress(&p_ad_, d_ad);
    float* p_h    = (float*)p_h_;
    float* p_g    = (float*)p_g_;
    float* p_hsum = (float*)p_hsum_;
    float* p_as   = (float*)p_as_;
    float* p_ad   = (float*)p_ad_;

    cudaFuncSetAttribute(mma_gemm_kernel,
                         cudaFuncAttributeMaxDynamicSharedMemorySize, SMEM_DYN);

    const int TPB = 256;
    const int eblocks = (E_TOT + TPB - 1) / TPB;
    const int gb = (N_NODES + 127) / 128;

    cudaStream_t s1 = g_s1, s2 = g_s2;

    // fork both worker streams from the capture-origin (legacy) stream
    cudaEventRecord(g_evA, 0);
    cudaStreamWaitEvent(s1, g_evA, 0);
    cudaStreamWaitEvent(s2, g_evA, 0);

    // ---- stream s2: graph build chain ----
    zero_kernel<<<(N_NODES + TPB - 1) / TPB, TPB, 0, s2>>>();
    hist_kernel<<<(E_EDGES + TPB - 1) / TPB, TPB, 0, s2>>>(ei);
    scanA_kernel<<<NB_SCAN, 1024, 0, s2>>>();
    scanC_kernel<<<NB_SCAN, 1024, 0, s2>>>();
    scatter_kernel<<<eblocks, TPB, 0, s2>>>(ei);
    cudaEventRecord(g_evB, s2);

    // ---- stream s1: GEMM chain (independent of build) ----
    // pre layer: h = relu(x@pre_w + pre_b); hsum = h
    mma_gemm_kernel<<<gb, 256, SMEM_DYN, s1>>>(x, F_INPUT, pre_w, pre_b, nullptr,
                                               p_h, p_hsum, nullptr, nullptr,
                                               N_NODES, 0);
    // GAT layer 1 linear part (also independent of build)
    mma_gemm_kernel<<<gb, 256, SMEM_DYN, s1>>>(p_h, HD, w1, asrc1, adst1,
                                               p_g, nullptr, p_as, p_ad,
                                               N_NODES, 1);

    // join: aggregation needs CSR + GEMM1 results
    cudaStreamWaitEvent(s1, g_evB, 0);
    agg_kernel<<<(N_NODES + 3) / 4, 128, 0, s1>>>(b1, 1);

    // GAT layer 2
    mma_gemm_kernel<<<gb, 256, SMEM_DYN, s1>>>(p_h, HD, w2, asrc2, adst2,
                                               p_g, nullptr, p_as, p_ad,
                                               N_NODES, 1);
    agg_kernel<<<(N_NODES + 3) / 4, 128, 0, s1>>>(b2, 0);   // d_h store is dead here

    // pooling + head
    pool_kernel<<<(N_NODES + 255) / 256, 128, 0, s1>>>(batch);
    final_kernel<<<G_GR, 128, 0, s1>>>(post_w1, post_b1, post_w2, post_b2, out);

    // join back to the capture-origin stream
    cudaEventRecord(g_evC, s1);
    cudaStreamWaitEvent(0, g_evC, 0);
}